// round 2
// baseline (speedup 1.0000x reference)
#include <cuda_runtime.h>
#include <cstdint>

// Problem constants (from reference)
#define NPTS 20000
#define NV   6
#define NP   64
#define ND   32

#define W_F  1600.0f
#define H_F  928.0f
#define EPSF 1e-5f

// Output layout (flatten + concat, float32):
//   xy_proj : (N, V, D, 2)  -> 7,680,000
//   mask    : (N, V, D)     -> 3,840,000
//   corr    : (N, V, P)     -> 7,680,000

__global__ __launch_bounds__(256) void boxcorr_kernel(
    const float* __restrict__ points,      // (N,3): [img_id, x, y]
    const float* __restrict__ trans_mats,  // (V,V,4,4)
    const float4* __restrict__ rois,       // (V,P,4) as float4
    float* __restrict__ out)
{
    __shared__ float  s_T[NV * NV * 16];   // 2304 B
    __shared__ float4 s_R[NV * NP];        // 6144 B

    const int tid = threadIdx.x;

    // Stage the tiny tables into shared once per block
    for (int i = tid; i < NV * NV * 16; i += 256) s_T[i] = trans_mats[i];
    for (int i = tid; i < NV * NP;      i += 256) s_R[i] = rois[i];
    __syncthreads();

    const int warp = blockIdx.x * 8 + (tid >> 5);   // one warp per (n, v)
    const int lane = tid & 31;
    if (warp >= NPTS * NV) return;
    const int n = warp / NV;
    const int v = warp - n * NV;

    // Point data (uniform across warp)
    const float idf = points[n * 3 + 0];
    const float x   = points[n * 3 + 1];
    const float y   = points[n * 3 + 2];
    const int   id  = (int)idf;

    // 4x4 transform rows 0..2 for (v, img_id), broadcast LDS.128
    const float4* Tm = (const float4*)&s_T[(v * NV + id) * 16];
    const float4 T0 = Tm[0];
    const float4 T1 = Tm[1];
    const float4 T2 = Tm[2];

    // LID depth for this lane, matching Python eval order:
    //   d = 0.5 + (bin_size * i) * (i + 1), bin_size computed in double
    const float binsz = (float)(69.5 / 1056.0);
    const float fi = (float)lane;
    const float d  = __fadd_rn(0.5f, __fmul_rn(__fmul_rn(binsz, fi), __fadd_rn(fi, 1.0f)));

    const float xd = __fmul_rn(x, d);
    const float yd = __fmul_rn(y, d);

    // proj = T @ [x*d, y*d, d, 1], ASCENDING-j fma accumulation
    // (acc = t0*b0; acc = fma(t1,b1,acc); acc = fma(t2,b2,acc); acc += t3)
    float px = __fmul_rn(T0.x, xd);
    px = __fmaf_rn(T0.y, yd, px);
    px = __fmaf_rn(T0.z, d,  px);
    px = __fadd_rn(px, T0.w);

    float py = __fmul_rn(T1.x, xd);
    py = __fmaf_rn(T1.y, yd, py);
    py = __fmaf_rn(T1.z, d,  py);
    py = __fadd_rn(py, T1.w);

    float z = __fmul_rn(T2.x, xd);
    z = __fmaf_rn(T2.y, yd, z);
    z = __fmaf_rn(T2.z, d,  z);
    z = __fadd_rn(z, T2.w);

    const float zc = fmaxf(z, EPSF);
    const float xq = __fdiv_rn(px, zc);
    const float yq = __fdiv_rn(py, zc);

    const bool valid = (z > EPSF) & (xq >= 0.0f) & (xq < W_F)
                                  & (yq >= 0.0f) & (yq < H_F);

    // ---- write xy_proj (coalesced: 32 consecutive float2 per warp) ----
    const size_t dbase = (size_t)warp * ND;   // (n*V + v) * D
    ((float2*)out)[dbase + lane] = make_float2(xq, yq);

    // ---- write mask ----
    float* maskout = out + (size_t)NPTS * NV * ND * 2;
    maskout[dbase + lane] = valid ? 1.0f : 0.0f;

    // ---- corr: each lane tests its depth against all 64 ROIs of view v ----
    const float4* Rv = &s_R[v * NP];
    unsigned m0 = 0u, m1 = 0u;
#pragma unroll
    for (int p = 0; p < 32; ++p) {
        const float4 r  = Rv[p];
        const bool inb  = valid & (xq > r.x) & (xq < r.z)
                                & (yq > r.y) & (yq < r.w);
        if (inb) m0 |= (1u << p);

        const float4 r2 = Rv[p + 32];
        const bool inb2 = valid & (xq > r2.x) & (xq < r2.z)
                                & (yq > r2.y) & (yq < r2.w);
        if (inb2) m1 |= (1u << p);
    }

    // OR over depth lanes: single REDUX.OR each
    m0 = __reduce_or_sync(0xffffffffu, m0);
    m1 = __reduce_or_sync(0xffffffffu, m1);

    // corr[n,v,p]: lane writes roi `lane` and roi `lane+32` (coalesced)
    float* corrout = out + (size_t)NPTS * NV * ND * 2 + (size_t)NPTS * NV * ND;
    const size_t cbase = (size_t)warp * NP;
    corrout[cbase + lane]      = ((m0 >> lane) & 1u) ? 1.0f : 0.0f;
    corrout[cbase + 32 + lane] = ((m1 >> lane) & 1u) ? 1.0f : 0.0f;
}

extern "C" void kernel_launch(void* const* d_in, const int* in_sizes, int n_in,
                              void* d_out, int out_size)
{
    const float*  points = (const float*)d_in[0];   // (N,3)
    const float*  trans  = (const float*)d_in[1];   // (V,V,4,4)
    const float4* rois   = (const float4*)d_in[2];  // (V,P,4)
    float* out = (float*)d_out;

    const int total_warps = NPTS * NV;              // 120000
    const int blocks = (total_warps + 7) / 8;       // 8 warps/block
    boxcorr_kernel<<<blocks, 256>>>(points, trans, rois, out);
}

// round 3
// speedup vs baseline: 4.8662x; 4.8662x over previous
#include <cuda_runtime.h>
#include <cstdint>

// Problem constants (from reference)
#define NPTS 20000
#define NV   6
#define NP   64
#define ND   32

#define W_F  1600.0f
#define H_F  928.0f
#define EPSF 1e-5f
#define FULLMASK 0xffffffffu

// Output layout (flatten + concat, float32):
//   xy_proj : (N, V, D, 2)  -> 7,680,000
//   mask    : (N, V, D)     -> 3,840,000
//   corr    : (N, V, P)     -> 7,680,000

__global__ __launch_bounds__(256) void boxcorr_kernel(
    const float* __restrict__ points,      // (N,3): [img_id, x, y]
    const float* __restrict__ trans_mats,  // (V,V,4,4)
    const float4* __restrict__ rois,       // (V,P,4) as float4
    float* __restrict__ out)
{
    __shared__ float  s_T[NV * NV * 16];   // 2304 B
    __shared__ float4 s_R[NV * NP];        // 6144 B

    const int tid = threadIdx.x;

    // Stage the tiny tables into shared once per block
    for (int i = tid; i < NV * NV * 16; i += 256) s_T[i] = trans_mats[i];
    for (int i = tid; i < NV * NP;      i += 256) s_R[i] = rois[i];
    __syncthreads();

    const int warp = blockIdx.x * 8 + (tid >> 5);   // one warp per (n, v)
    const int lane = tid & 31;
    if (warp >= NPTS * NV) return;
    const int n = warp / NV;
    const int v = warp - n * NV;

    // Point data (uniform across warp)
    const float idf = points[n * 3 + 0];
    const float x   = points[n * 3 + 1];
    const float y   = points[n * 3 + 2];
    const int   id  = (int)idf;

    // 4x4 transform rows 0..2 for (v, img_id), broadcast LDS.128
    const float4* Tm = (const float4*)&s_T[(v * NV + id) * 16];
    const float4 T0 = Tm[0];
    const float4 T1 = Tm[1];
    const float4 T2 = Tm[2];

    // LID depth for this lane, matching Python eval order (bit-exact):
    const float binsz = (float)(69.5 / 1056.0);
    const float fi = (float)lane;
    const float d  = __fadd_rn(0.5f, __fmul_rn(__fmul_rn(binsz, fi), __fadd_rn(fi, 1.0f)));

    const float xd = __fmul_rn(x, d);
    const float yd = __fmul_rn(y, d);

    // proj = T @ [x*d, y*d, d, 1], ascending-j fma accumulation (matches XLA)
    float px = __fmul_rn(T0.x, xd);
    px = __fmaf_rn(T0.y, yd, px);
    px = __fmaf_rn(T0.z, d,  px);
    px = __fadd_rn(px, T0.w);

    float py = __fmul_rn(T1.x, xd);
    py = __fmaf_rn(T1.y, yd, py);
    py = __fmaf_rn(T1.z, d,  py);
    py = __fadd_rn(py, T1.w);

    float z = __fmul_rn(T2.x, xd);
    z = __fmaf_rn(T2.y, yd, z);
    z = __fmaf_rn(T2.z, d,  z);
    z = __fadd_rn(z, T2.w);

    const float zc = fmaxf(z, EPSF);
    const float xq = __fdiv_rn(px, zc);
    const float yq = __fdiv_rn(py, zc);

    const bool valid = (z > EPSF) & (xq >= 0.0f) & (xq < W_F)
                                  & (yq >= 0.0f) & (yq < H_F);

    // ---- write xy_proj (coalesced: 32 consecutive float2 per warp) ----
    const size_t dbase = (size_t)warp * ND;   // (n*V + v) * D
    ((float2*)out)[dbase + lane] = make_float2(xq, yq);

    // ---- write mask ----
    float* maskout = out + (size_t)NPTS * NV * ND * 2;
    maskout[dbase + lane] = valid ? 1.0f : 0.0f;

    // ---- warp bbox over VALID points (uint bit-order == float order for >=0) ----
    // sanitize -0.0 -> +0.0 (compares identically, keeps uint order monotone)
    const unsigned xb = __float_as_uint(xq) & 0x7fffffffu;
    const unsigned yb = __float_as_uint(yq) & 0x7fffffffu;
    const unsigned minxb = __reduce_min_sync(FULLMASK, valid ? xb : 0x7f800000u);
    const unsigned maxxb = __reduce_max_sync(FULLMASK, valid ? xb : 0u);
    const unsigned minyb = __reduce_min_sync(FULLMASK, valid ? yb : 0x7f800000u);
    const unsigned maxyb = __reduce_max_sync(FULLMASK, valid ? yb : 0u);
    const float minx = __uint_as_float(minxb);
    const float maxx = __uint_as_float(maxxb);
    const float miny = __uint_as_float(minyb);
    const float maxy = __uint_as_float(maxyb);

    // ---- candidate ROI mask: lane tests ROI[lane] and ROI[lane+32] vs bbox ----
    // (necessary condition for any point to be strictly inside the ROI)
    const float4* Rv = &s_R[v * NP];
    const float4 ra = Rv[lane];
    const float4 rb = Rv[lane + 32];
    const bool ca = (maxx > ra.x) & (minx < ra.z) & (maxy > ra.y) & (miny < ra.w);
    const bool cb = (maxx > rb.x) & (minx < rb.z) & (maxy > rb.y) & (miny < rb.w);
    unsigned b0 = __ballot_sync(FULLMASK, ca);   // candidates among ROIs 0..31
    unsigned b1 = __ballot_sync(FULLMASK, cb);   // candidates among ROIs 32..63

    // ---- exact test only for candidate ROIs; ballot collapses the depth dim ----
    unsigned mm0 = 0u, mm1 = 0u;
    while (b0) {
        const int p = __ffs(b0) - 1;
        b0 &= b0 - 1;
        const float4 r = Rv[p];                   // broadcast LDS
        const bool inb = valid & (xq > r.x) & (xq < r.z)
                               & (yq > r.y) & (yq < r.w);
        if (__ballot_sync(FULLMASK, inb)) mm0 |= (1u << p);
    }
    while (b1) {
        const int p = __ffs(b1) - 1;
        b1 &= b1 - 1;
        const float4 r = Rv[p + 32];
        const bool inb = valid & (xq > r.x) & (xq < r.z)
                               & (yq > r.y) & (yq < r.w);
        if (__ballot_sync(FULLMASK, inb)) mm1 |= (1u << p);
    }

    // corr[n,v,p]: lane writes roi `lane` and roi `lane+32` (coalesced)
    float* corrout = out + (size_t)NPTS * NV * ND * 2 + (size_t)NPTS * NV * ND;
    const size_t cbase = (size_t)warp * NP;
    corrout[cbase + lane]      = ((mm0 >> lane) & 1u) ? 1.0f : 0.0f;
    corrout[cbase + 32 + lane] = ((mm1 >> lane) & 1u) ? 1.0f : 0.0f;
}

extern "C" void kernel_launch(void* const* d_in, const int* in_sizes, int n_in,
                              void* d_out, int out_size)
{
    const float*  points = (const float*)d_in[0];   // (N,3)
    const float*  trans  = (const float*)d_in[1];   // (V,V,4,4)
    const float4* rois   = (const float4*)d_in[2];  // (V,P,4)
    float* out = (float*)d_out;

    const int total_warps = NPTS * NV;              // 120000
    const int blocks = (total_warps + 7) / 8;       // 8 warps/block
    boxcorr_kernel<<<blocks, 256>>>(points, trans, rois, out);
}

// round 4
// speedup vs baseline: 8.2799x; 1.7015x over previous
#include <cuda_runtime.h>
#include <cstdint>

// Problem constants (from reference)
#define NPTS 20000
#define NV   6
#define NP   64
#define ND   32

#define W_F  1600.0f
#define H_F  928.0f
#define EPSF 1e-5f
#define FULLMASK 0xffffffffu

// Output layout (flatten + concat, float32):
//   xy_proj : (N, V, D, 2)  -> 7,680,000
//   mask    : (N, V, D)     -> 3,840,000
//   corr    : (N, V, P)     -> 7,680,000

__global__ __launch_bounds__(256) void boxcorr_kernel(
    const float* __restrict__ points,      // (N,3): [img_id, x, y]
    const float* __restrict__ trans_mats,  // (V,V,4,4)
    const float4* __restrict__ rois,       // (V,P,4) as float4
    float* __restrict__ out)
{
    const int warpid = blockIdx.x * 8 + (threadIdx.x >> 5);  // one warp per point
    const int lane   = threadIdx.x & 31;
    if (warpid >= NPTS) return;
    const int n = warpid;

    // Point data (uniform across warp) — loaded ONCE per point
    const float idf = __ldg(points + n * 3 + 0);
    const float x   = __ldg(points + n * 3 + 1);
    const float y   = __ldg(points + n * 3 + 2);
    const int   id  = (int)idf;

    // LID depth for this lane, matching Python eval order (bit-exact) — once per point
    const float binsz = (float)(69.5 / 1056.0);
    const float fi = (float)lane;
    const float d  = __fadd_rn(0.5f, __fmul_rn(__fmul_rn(binsz, fi), __fadd_rn(fi, 1.0f)));
    const float xd = __fmul_rn(x, d);
    const float yd = __fmul_rn(y, d);

    float* maskout = out + (size_t)NPTS * NV * ND * 2;
    float* corrout = out + (size_t)NPTS * NV * ND * 2 + (size_t)NPTS * NV * ND;

#pragma unroll
    for (int v = 0; v < NV; ++v) {
        // 4x4 transform rows 0..2 for (v, img_id) — uniform LDG.128, L1 hot
        const float4* Tm = (const float4*)(trans_mats + (v * NV + id) * 16);
        const float4 T0 = __ldg(Tm + 0);
        const float4 T1 = __ldg(Tm + 1);
        const float4 T2 = __ldg(Tm + 2);

        // proj = T @ [x*d, y*d, d, 1], ascending-j fma accumulation (matches XLA)
        float px = __fmul_rn(T0.x, xd);
        px = __fmaf_rn(T0.y, yd, px);
        px = __fmaf_rn(T0.z, d,  px);
        px = __fadd_rn(px, T0.w);

        float py = __fmul_rn(T1.x, xd);
        py = __fmaf_rn(T1.y, yd, py);
        py = __fmaf_rn(T1.z, d,  py);
        py = __fadd_rn(py, T1.w);

        float z = __fmul_rn(T2.x, xd);
        z = __fmaf_rn(T2.y, yd, z);
        z = __fmaf_rn(T2.z, d,  z);
        z = __fadd_rn(z, T2.w);

        const float zc = fmaxf(z, EPSF);
        const float xq = __fdiv_rn(px, zc);
        const float yq = __fdiv_rn(py, zc);

        const bool valid = (z > EPSF) & (xq >= 0.0f) & (xq < W_F)
                                      & (yq >= 0.0f) & (yq < H_F);

        // ---- write xy_proj + mask (coalesced per warp) ----
        const size_t dbase = ((size_t)n * NV + v) * ND;
        ((float2*)out)[dbase + lane] = make_float2(xq, yq);
        maskout[dbase + lane] = valid ? 1.0f : 0.0f;

        unsigned mm0 = 0u, mm1 = 0u;
        const unsigned vmask = __ballot_sync(FULLMASK, valid);
        if (vmask) {   // warp-uniform branch; skip all corr work if no valid depth
            // warp bbox over VALID points (uint order == float order for >=0)
            const unsigned xb = __float_as_uint(xq) & 0x7fffffffu;
            const unsigned yb = __float_as_uint(yq) & 0x7fffffffu;
            const float minx = __uint_as_float(__reduce_min_sync(FULLMASK, valid ? xb : 0x7f800000u));
            const float maxx = __uint_as_float(__reduce_max_sync(FULLMASK, valid ? xb : 0u));
            const float miny = __uint_as_float(__reduce_min_sync(FULLMASK, valid ? yb : 0x7f800000u));
            const float maxy = __uint_as_float(__reduce_max_sync(FULLMASK, valid ? yb : 0u));

            // candidate ROI mask: lane tests ROI[lane], ROI[lane+32] vs bbox
            const float4* Rv = rois + v * NP;
            const float4 ra = __ldg(Rv + lane);
            const float4 rb = __ldg(Rv + lane + 32);
            const bool ca = (maxx > ra.x) & (minx < ra.z) & (maxy > ra.y) & (miny < ra.w);
            const bool cb = (maxx > rb.x) & (minx < rb.z) & (maxy > rb.y) & (miny < rb.w);
            unsigned b0 = __ballot_sync(FULLMASK, ca);
            unsigned b1 = __ballot_sync(FULLMASK, cb);

            // exact test only for candidates; ballot collapses the depth dim
            while (b0) {
                const int p = __ffs(b0) - 1;
                b0 &= b0 - 1;
                const float4 r = __ldg(Rv + p);          // uniform LDG, L1 hot
                const bool inb = valid & (xq > r.x) & (xq < r.z)
                                       & (yq > r.y) & (yq < r.w);
                if (__ballot_sync(FULLMASK, inb)) mm0 |= (1u << p);
            }
            while (b1) {
                const int p = __ffs(b1) - 1;
                b1 &= b1 - 1;
                const float4 r = __ldg(Rv + p + 32);
                const bool inb = valid & (xq > r.x) & (xq < r.z)
                                       & (yq > r.y) & (yq < r.w);
                if (__ballot_sync(FULLMASK, inb)) mm1 |= (1u << p);
            }
        }

        // corr[n,v,p]: lane writes roi `lane` and roi `lane+32` (coalesced)
        const size_t cbase = dbase * 2;    // ((n*NV+v)*64)
        corrout[cbase + lane]      = ((mm0 >> lane) & 1u) ? 1.0f : 0.0f;
        corrout[cbase + 32 + lane] = ((mm1 >> lane) & 1u) ? 1.0f : 0.0f;
    }
}

extern "C" void kernel_launch(void* const* d_in, const int* in_sizes, int n_in,
                              void* d_out, int out_size)
{
    const float*  points = (const float*)d_in[0];   // (N,3)
    const float*  trans  = (const float*)d_in[1];   // (V,V,4,4)
    const float4* rois   = (const float4*)d_in[2];  // (V,P,4)
    float* out = (float*)d_out;

    const int total_warps = NPTS;                   // one warp per point
    const int blocks = (total_warps + 7) / 8;       // 8 warps/block -> 2500 blocks
    boxcorr_kernel<<<blocks, 256>>>(points, trans, rois, out);
}